// round 1
// baseline (speedup 1.0000x reference)
#include <cuda_runtime.h>
#include <math.h>

#define NN 100000
#define NE 3200000
#define DIN 64
#define DH  40
#define DOUT 24

// ---------------- scratch (static device globals; no allocation) -------------
__device__ __align__(16) float g_xl[NN * DH];    // x @ W1_l^T
__device__ __align__(16) float g_s1[NN * DH];    // scatter sum layer 1
__device__ __align__(16) float g_h [NN * DH];    // relu hidden
__device__ __align__(16) float g_hl[NN * DOUT];  // h @ W2_l^T
__device__ __align__(16) float g_hr[NN * DOUT];  // h @ W2_r^T + b2
__device__ __align__(16) float g_s2[NN * DOUT];  // scatter sum layer 2
__device__ __align__(16) float g_cnt[NN];        // in-degree

// ---------------- zero the accumulators --------------------------------------
__global__ void k_zero() {
    int t = blockIdx.x * blockDim.x + threadIdx.x;
    int stride = gridDim.x * blockDim.x;
    for (int i = t; i < NN * DH;   i += stride) g_s1[i] = 0.f;
    for (int i = t; i < NN * DOUT; i += stride) g_s2[i] = 0.f;
    for (int i = t; i < NN;        i += stride) g_cnt[i] = 0.f;
}

// ---------------- xl = x @ W1_l^T  (64 -> 40) --------------------------------
// 64 nodes per block, 256 threads. W padded to 68 floats/row (bank-conflict free).
__global__ __launch_bounds__(256) void k_gemm_xl(const float* __restrict__ x,
                                                 const float* __restrict__ W1l) {
    __shared__ float sW[DH * 68];
    __shared__ float xs[64 * DIN];
    int tid = threadIdx.x;
    int n0  = blockIdx.x * 64;

    for (int i = tid; i < DH * DIN; i += 256)
        sW[(i / DIN) * 68 + (i % DIN)] = W1l[i];

    const float4* x4  = (const float4*)x;
    float4*       xs4 = (float4*)xs;
    for (int i = tid; i < 64 * 16; i += 256) {
        int node = i >> 4, kk = i & 15;
        int n = n0 + node;
        xs4[i] = (n < NN) ? x4[n * 16 + kk] : make_float4(0.f, 0.f, 0.f, 0.f);
    }
    __syncthreads();

    const float4* sW4 = (const float4*)sW;
    #pragma unroll
    for (int it = 0; it < 10; ++it) {
        int w = it * 256 + tid;           // < 2560
        int node = w / DH, j = w % DH;
        if (n0 + node >= NN) continue;
        float acc = 0.f;
        #pragma unroll
        for (int kk = 0; kk < 16; ++kk) {
            float4 a = xs4[node * 16 + kk];
            float4 b = sW4[j * 17 + kk];
            acc += a.x * b.x + a.y * b.y + a.z * b.z + a.w * b.w;
        }
        g_xl[n0 * DH + w] = acc;
    }
}

// ---------------- scatter layer 1: s1[dst] += xl[src], cnt[dst] += 1 ---------
// 10 threads per edge, one float4 each (row = 160B contiguous).
__global__ void k_scatter1(const int* __restrict__ src, const int* __restrict__ dst) {
    unsigned t = blockIdx.x * blockDim.x + threadIdx.x;
    if (t >= (unsigned)NE * 10u) return;
    unsigned e = t / 10u, c = t - e * 10u;
    int s = src[e], d = dst[e];
    float4 v = ((const float4*)g_xl)[s * 10 + c];
    float* p = &g_s1[d * DH + c * 4];
    asm volatile("red.global.add.v4.f32 [%0], {%1,%2,%3,%4};"
                 :: "l"(p), "f"(v.x), "f"(v.y), "f"(v.z), "f"(v.w) : "memory");
    if (c == 0) atomicAdd(&g_cnt[d], 1.0f);
}

// ---------------- h = relu(s1/max(cnt,1) + b1 + x @ W1_r^T) ------------------
__global__ __launch_bounds__(256) void k_gemm_h(const float* __restrict__ x,
                                                const float* __restrict__ W1r,
                                                const float* __restrict__ b1) {
    __shared__ float sW[DH * 68];
    __shared__ float xs[64 * DIN];
    __shared__ float sb[DH];
    int tid = threadIdx.x;
    int n0  = blockIdx.x * 64;

    for (int i = tid; i < DH * DIN; i += 256)
        sW[(i / DIN) * 68 + (i % DIN)] = W1r[i];
    if (tid < DH) sb[tid] = b1[tid];

    const float4* x4  = (const float4*)x;
    float4*       xs4 = (float4*)xs;
    for (int i = tid; i < 64 * 16; i += 256) {
        int node = i >> 4, kk = i & 15;
        int n = n0 + node;
        xs4[i] = (n < NN) ? x4[n * 16 + kk] : make_float4(0.f, 0.f, 0.f, 0.f);
    }
    __syncthreads();

    const float4* sW4 = (const float4*)sW;
    #pragma unroll
    for (int it = 0; it < 10; ++it) {
        int w = it * 256 + tid;
        int node = w / DH, j = w % DH;
        int n = n0 + node;
        if (n >= NN) continue;
        float inv = __fdividef(1.f, fmaxf(g_cnt[n], 1.f));
        float acc = g_s1[n0 * DH + w] * inv + sb[j];
        #pragma unroll
        for (int kk = 0; kk < 16; ++kk) {
            float4 a = xs4[node * 16 + kk];
            float4 b = sW4[j * 17 + kk];
            acc += a.x * b.x + a.y * b.y + a.z * b.z + a.w * b.w;
        }
        g_h[n0 * DH + w] = fmaxf(acc, 0.f);
    }
}

// ---------------- hl = h @ W2_l^T ; hr = h @ W2_r^T + b2  (40 -> 24) ---------
__global__ __launch_bounds__(256) void k_gemm_l2(const float* __restrict__ W2l,
                                                 const float* __restrict__ W2r,
                                                 const float* __restrict__ b2) {
    __shared__ float hs[64 * DH];
    __shared__ float sWl[DOUT * 44];
    __shared__ float sWr[DOUT * 44];
    __shared__ float sb[DOUT];
    int tid = threadIdx.x;
    int n0  = blockIdx.x * 64;

    for (int i = tid; i < DOUT * DH; i += 256) {
        int j = i / DH, k = i % DH;
        sWl[j * 44 + k] = W2l[i];
        sWr[j * 44 + k] = W2r[i];
    }
    if (tid < DOUT) sb[tid] = b2[tid];

    const float4* h4  = (const float4*)g_h;
    float4*       hs4 = (float4*)hs;
    for (int i = tid; i < 64 * 10; i += 256) {
        int node = i / 10, kk = i % 10;
        int n = n0 + node;
        hs4[i] = (n < NN) ? h4[n * 10 + kk] : make_float4(0.f, 0.f, 0.f, 0.f);
    }
    __syncthreads();

    const float4* sWl4 = (const float4*)sWl;
    const float4* sWr4 = (const float4*)sWr;
    #pragma unroll
    for (int it = 0; it < 6; ++it) {
        int w = it * 256 + tid;           // < 1536
        int node = w / DOUT, j = w % DOUT;
        if (n0 + node >= NN) continue;
        float accl = 0.f;
        float accr = sb[j];
        #pragma unroll
        for (int kk = 0; kk < 10; ++kk) {
            float4 a  = hs4[node * 10 + kk];
            float4 bl = sWl4[j * 11 + kk];
            float4 br = sWr4[j * 11 + kk];
            accl += a.x * bl.x + a.y * bl.y + a.z * bl.z + a.w * bl.w;
            accr += a.x * br.x + a.y * br.y + a.z * br.z + a.w * br.w;
        }
        g_hl[n0 * DOUT + w] = accl;
        g_hr[n0 * DOUT + w] = accr;
    }
}

// ---------------- scatter layer 2: s2[dst] += hl[src] ------------------------
// 6 threads per edge, one float4 each (row = 96B contiguous).
__global__ void k_scatter2(const int* __restrict__ src, const int* __restrict__ dst) {
    unsigned t = blockIdx.x * blockDim.x + threadIdx.x;
    if (t >= (unsigned)NE * 6u) return;
    unsigned e = t / 6u, c = t - e * 6u;
    int s = src[e], d = dst[e];
    float4 v = ((const float4*)g_hl)[s * 6 + c];
    float* p = &g_s2[d * DOUT + c * 4];
    asm volatile("red.global.add.v4.f32 [%0], {%1,%2,%3,%4};"
                 :: "l"(p), "f"(v.x), "f"(v.y), "f"(v.z), "f"(v.w) : "memory");
}

// ---------------- out = log_softmax(s2/max(cnt,1) + hr) ----------------------
__global__ void k_final(float* __restrict__ out) {
    int n = blockIdx.x * blockDim.x + threadIdx.x;
    if (n >= NN) return;
    float inv = __fdividef(1.f, fmaxf(g_cnt[n], 1.f));
    const float4* s24 = (const float4*)g_s2;
    const float4* hr4 = (const float4*)g_hr;
    float v[DOUT];
    #pragma unroll
    for (int kk = 0; kk < 6; ++kk) {
        float4 a = s24[n * 6 + kk];
        float4 b = hr4[n * 6 + kk];
        v[kk * 4 + 0] = a.x * inv + b.x;
        v[kk * 4 + 1] = a.y * inv + b.y;
        v[kk * 4 + 2] = a.z * inv + b.z;
        v[kk * 4 + 3] = a.w * inv + b.w;
    }
    float m = v[0];
    #pragma unroll
    for (int j = 1; j < DOUT; ++j) m = fmaxf(m, v[j]);
    float s = 0.f;
    #pragma unroll
    for (int j = 0; j < DOUT; ++j) s += expf(v[j] - m);
    float l = m + logf(s);
    float4* o4 = (float4*)out;
    #pragma unroll
    for (int kk = 0; kk < 6; ++kk) {
        float4 r;
        r.x = v[kk * 4 + 0] - l;
        r.y = v[kk * 4 + 1] - l;
        r.z = v[kk * 4 + 2] - l;
        r.w = v[kk * 4 + 3] - l;
        o4[n * 6 + kk] = r;
    }
}

// ---------------- launch ------------------------------------------------------
extern "C" void kernel_launch(void* const* d_in, const int* in_sizes, int n_in,
                              void* d_out, int out_size) {
    const float* x   = (const float*)d_in[0];
    const int*   ei  = (const int*)  d_in[1];
    const float* W1l = (const float*)d_in[2];
    const float* b1  = (const float*)d_in[3];
    const float* W1r = (const float*)d_in[4];
    const float* W2l = (const float*)d_in[5];
    const float* b2  = (const float*)d_in[6];
    const float* W2r = (const float*)d_in[7];
    float* out = (float*)d_out;

    const int* src = ei;            // edge_index[0]
    const int* dst = ei + NE;       // edge_index[1]

    const int nblk = (NN + 63) / 64;   // 1563

    k_zero<<<2048, 256>>>();
    k_gemm_xl<<<nblk, 256>>>(x, W1l);
    {
        unsigned T = (unsigned)NE * 10u;
        k_scatter1<<<(T + 255) / 256, 256>>>(src, dst);
    }
    k_gemm_h<<<nblk, 256>>>(x, W1r, b1);
    k_gemm_l2<<<nblk, 256>>>(W2l, W2r, b2);
    {
        unsigned T = (unsigned)NE * 6u;
        k_scatter2<<<(T + 255) / 256, 256>>>(src, dst);
    }
    k_final<<<(NN + 255) / 256, 256>>>(out);
}

// round 3
// speedup vs baseline: 1.2292x; 1.2292x over previous
#include <cuda_runtime.h>
#include <math.h>

#define NN   100000
#define NE   3200000
#define DIN  64
#define DH   40
#define DOUT 24
#define NBLK_SCAN 98   // ceil(NN / 1024)

// ---------------- scratch (static device globals; no allocation) -------------
__device__ __align__(16) float g_xl[NN * DH];    // x @ W1_l^T
__device__ __align__(16) float g_s1[NN * DH];    // mean-aggregated xl
__device__ __align__(16) float g_h [NN * DH];    // relu hidden
__device__ __align__(16) float g_hl[NN * DOUT];  // h @ W2_l^T
__device__ __align__(16) float g_hr[NN * DOUT];  // h @ W2_r^T + b2
__device__ int g_deg[NN];
__device__ int g_rowptr[NN + 1];
__device__ int g_wptr[NN];
__device__ int g_srcs[NE];                       // src sorted by dst (CSR adjacency)
__device__ int g_bsum[NBLK_SCAN];
__device__ int g_boff[NBLK_SCAN];

// ---------------- f32x2 packed-FMA helpers -----------------------------------
__device__ __forceinline__ unsigned long long fma2(unsigned long long a,
                                                   unsigned long long b,
                                                   unsigned long long c) {
    unsigned long long d;
    asm("fma.rn.f32x2 %0, %1, %2, %3;" : "=l"(d) : "l"(a), "l"(b), "l"(c));
    return d;
}
__device__ __forceinline__ float hadd2(unsigned long long a) {
    float lo, hi;
    asm("mov.b64 {%0,%1}, %2;" : "=f"(lo), "=f"(hi) : "l"(a));
    return lo + hi;
}

// ---------------- CSR build ---------------------------------------------------
__global__ void k_zero_deg() {
    int t = blockIdx.x * blockDim.x + threadIdx.x;
    for (int i = t; i < NN; i += gridDim.x * blockDim.x) g_deg[i] = 0;
}

__global__ void k_hist(const int* __restrict__ dst) {
    int e = blockIdx.x * blockDim.x + threadIdx.x;
    if (e < NE) atomicAdd(&g_deg[dst[e]], 1);
}

// block-local exclusive scan of 1024 elems (256 threads x 4)
__global__ __launch_bounds__(256) void k_scan1() {
    __shared__ int warp_sums[8];
    int tid = threadIdx.x;
    int base = blockIdx.x * 1024 + tid * 4;
    int v[4];
#pragma unroll
    for (int q = 0; q < 4; ++q) {
        int idx = base + q;
        v[q] = (idx < NN) ? g_deg[idx] : 0;
    }
    int s = v[0] + v[1] + v[2] + v[3];
    int lane = tid & 31, wid = tid >> 5;
    int incl = s;
#pragma unroll
    for (int o = 1; o < 32; o <<= 1) {
        int t = __shfl_up_sync(0xffffffffu, incl, o);
        if (lane >= o) incl += t;
    }
    if (lane == 31) warp_sums[wid] = incl;
    __syncthreads();
    if (wid == 0) {
        int ws = (lane < 8) ? warp_sums[lane] : 0;
#pragma unroll
        for (int o = 1; o < 8; o <<= 1) {
            int t = __shfl_up_sync(0xffffffffu, ws, o);
            if (lane >= o) ws += t;
        }
        if (lane < 8) warp_sums[lane] = ws;   // inclusive over warps
    }
    __syncthreads();
    int excl = incl - s + (wid ? warp_sums[wid - 1] : 0);
    int run = excl;
#pragma unroll
    for (int q = 0; q < 4; ++q) {
        int idx = base + q;
        if (idx < NN) g_rowptr[idx] = run;
        run += v[q];
    }
    if (tid == 255) g_bsum[blockIdx.x] = warp_sums[7];
}

__global__ void k_scan2() {
    int acc = 0;
    for (int b = 0; b < NBLK_SCAN; ++b) { g_boff[b] = acc; acc += g_bsum[b]; }
    g_rowptr[NN] = acc;   // == NE
}

__global__ __launch_bounds__(256) void k_scan3() {
    int off = g_boff[blockIdx.x];
    int base = blockIdx.x * 1024 + threadIdx.x * 4;
#pragma unroll
    for (int q = 0; q < 4; ++q) {
        int idx = base + q;
        if (idx < NN) {
            int r = g_rowptr[idx] + off;
            g_rowptr[idx] = r;
            g_wptr[idx]   = r;
        }
    }
}

__global__ void k_place(const int* __restrict__ src, const int* __restrict__ dst) {
    int e = blockIdx.x * blockDim.x + threadIdx.x;
    if (e < NE) {
        int d = dst[e];
        int p = atomicAdd(&g_wptr[d], 1);
        g_srcs[p] = src[e];
    }
}

// ---------------- xl = x @ W1_l^T  (64 -> 40), thread-per-node ---------------
__global__ __launch_bounds__(256) void k_gemm_xl(const float* __restrict__ x,
                                                 const float* __restrict__ W1l) {
    __shared__ unsigned long long sW[DH * DIN / 2];   // 1280 pairs, 10KB
    int tid = threadIdx.x;
    for (int i = tid; i < DH * DIN / 2; i += 256)
        sW[i] = ((const unsigned long long*)W1l)[i];
    __syncthreads();

    int n = blockIdx.x * 256 + tid;
    if (n >= NN) return;

    unsigned long long xr[DIN / 2];
    const ulonglong2* xp = (const ulonglong2*)(x + (size_t)n * DIN);
#pragma unroll
    for (int q = 0; q < DIN / 4; ++q) {   // 16 LDG.128 -> 64 floats
        ulonglong2 t = xp[q];
        xr[2 * q] = t.x; xr[2 * q + 1] = t.y;
    }
    float* orow = g_xl + (size_t)n * DH;
    for (int j = 0; j < DH; j += 2) {
        unsigned long long a0 = 0ull, a1 = 0ull;
        const unsigned long long* w0 = sW + j * (DIN / 2);
        const unsigned long long* w1 = w0 + (DIN / 2);
#pragma unroll
        for (int p = 0; p < DIN / 2; ++p) {
            a0 = fma2(xr[p], w0[p], a0);
            a1 = fma2(xr[p], w1[p], a1);
        }
        float2 o; o.x = hadd2(a0); o.y = hadd2(a1);
        *(float2*)(orow + j) = o;
    }
}

// ---------------- agg1: s1[n] = mean over edges of xl[src] -------------------
// one warp per destination node; lanes 0-31 = feats 0-31, lanes 0-7 also 32-39
__global__ __launch_bounds__(256) void k_agg1() {
    int w = blockIdx.x * 8 + (threadIdx.x >> 5);
    int lane = threadIdx.x & 31;
    if (w >= NN) return;
    int beg = g_rowptr[w], end = g_rowptr[w + 1];
    float a0 = 0.f, a1 = 0.f;
    int i = beg;
    for (; i + 32 <= end; i += 32) {
        int sv = g_srcs[i + lane];
#pragma unroll
        for (int j = 0; j < 32; ++j) {
            int sj = __shfl_sync(0xffffffffu, sv, j);
            const float* row = g_xl + (size_t)sj * DH;
            a0 += row[lane];
            if (lane < 8) a1 += row[32 + lane];
        }
    }
    int rem = end - i;
    if (rem > 0) {
        int sv = (lane < rem) ? g_srcs[i + lane] : 0;
        for (int j = 0; j < rem; ++j) {
            int sj = __shfl_sync(0xffffffffu, sv, j);
            const float* row = g_xl + (size_t)sj * DH;
            a0 += row[lane];
            if (lane < 8) a1 += row[32 + lane];
        }
    }
    float inv = (end > beg) ? 1.f / (float)(end - beg) : 0.f;
    g_s1[(size_t)w * DH + lane] = a0 * inv;
    if (lane < 8) g_s1[(size_t)w * DH + 32 + lane] = a1 * inv;
}

// ---------------- h = relu(s1 + b1 + x @ W1_r^T) ------------------------------
__global__ __launch_bounds__(256) void k_gemm_h(const float* __restrict__ x,
                                                const float* __restrict__ W1r,
                                                const float* __restrict__ b1) {
    __shared__ unsigned long long sW[DH * DIN / 2];
    __shared__ float sb[DH];
    int tid = threadIdx.x;
    for (int i = tid; i < DH * DIN / 2; i += 256)
        sW[i] = ((const unsigned long long*)W1r)[i];
    if (tid < DH) sb[tid] = b1[tid];
    __syncthreads();

    int n = blockIdx.x * 256 + tid;
    if (n >= NN) return;

    unsigned long long xr[DIN / 2];
    const ulonglong2* xp = (const ulonglong2*)(x + (size_t)n * DIN);
#pragma unroll
    for (int q = 0; q < DIN / 4; ++q) {   // 16 LDG.128 -> 64 floats
        ulonglong2 t = xp[q];
        xr[2 * q] = t.x; xr[2 * q + 1] = t.y;
    }
    float sres[DH];
    const float4* s14 = (const float4*)(g_s1 + (size_t)n * DH);
#pragma unroll
    for (int q = 0; q < DH / 4; ++q) ((float4*)sres)[q] = s14[q];

    float* orow = g_h + (size_t)n * DH;
    for (int j = 0; j < DH; j += 2) {
        unsigned long long a0 = 0ull, a1 = 0ull;
        const unsigned long long* w0 = sW + j * (DIN / 2);
        const unsigned long long* w1 = w0 + (DIN / 2);
#pragma unroll
        for (int p = 0; p < DIN / 2; ++p) {
            a0 = fma2(xr[p], w0[p], a0);
            a1 = fma2(xr[p], w1[p], a1);
        }
        float r0 = hadd2(a0) + sres[j]     + sb[j];
        float r1 = hadd2(a1) + sres[j + 1] + sb[j + 1];
        float2 o; o.x = fmaxf(r0, 0.f); o.y = fmaxf(r1, 0.f);
        *(float2*)(orow + j) = o;
    }
}

// ---------------- hl = h @ W2_l^T ; hr = h @ W2_r^T + b2 ----------------------
__global__ __launch_bounds__(256) void k_gemm_l2(const float* __restrict__ W2l,
                                                 const float* __restrict__ W2r,
                                                 const float* __restrict__ b2) {
    __shared__ unsigned long long sWl[DOUT * DH / 2];   // 480 pairs
    __shared__ unsigned long long sWr[DOUT * DH / 2];
    __shared__ float sb[DOUT];
    int tid = threadIdx.x;
    for (int i = tid; i < DOUT * DH / 2; i += 256) {
        sWl[i] = ((const unsigned long long*)W2l)[i];
        sWr[i] = ((const unsigned long long*)W2r)[i];
    }
    if (tid < DOUT) sb[tid] = b2[tid];
    __syncthreads();

    int n = blockIdx.x * 256 + tid;
    if (n >= NN) return;

    unsigned long long hr2[DH / 2];
    const ulonglong2* hp = (const ulonglong2*)(g_h + (size_t)n * DH);
#pragma unroll
    for (int q = 0; q < DH / 4; ++q) {    // 10 LDG.128 -> 40 floats
        ulonglong2 t = hp[q];
        hr2[2 * q] = t.x; hr2[2 * q + 1] = t.y;
    }
    float* ol = g_hl + (size_t)n * DOUT;
    float* orr = g_hr + (size_t)n * DOUT;
    for (int j = 0; j < DOUT; j += 2) {
        unsigned long long al0 = 0ull, al1 = 0ull, ar0 = 0ull, ar1 = 0ull;
        const unsigned long long* wl0 = sWl + j * (DH / 2);
        const unsigned long long* wl1 = wl0 + (DH / 2);
        const unsigned long long* wr0 = sWr + j * (DH / 2);
        const unsigned long long* wr1 = wr0 + (DH / 2);
#pragma unroll
        for (int p = 0; p < DH / 2; ++p) {
            al0 = fma2(hr2[p], wl0[p], al0);
            al1 = fma2(hr2[p], wl1[p], al1);
            ar0 = fma2(hr2[p], wr0[p], ar0);
            ar1 = fma2(hr2[p], wr1[p], ar1);
        }
        float2 vl; vl.x = hadd2(al0); vl.y = hadd2(al1);
        float2 vr; vr.x = hadd2(ar0) + sb[j]; vr.y = hadd2(ar1) + sb[j + 1];
        *(float2*)(ol + j)  = vl;
        *(float2*)(orr + j) = vr;
    }
}

// ---------------- agg2 + log_softmax fused ------------------------------------
// one warp per node; lanes 0-23 = output features
__global__ __launch_bounds__(256) void k_agg2_final(float* __restrict__ out) {
    int w = blockIdx.x * 8 + (threadIdx.x >> 5);
    int lane = threadIdx.x & 31;
    if (w >= NN) return;
    int beg = g_rowptr[w], end = g_rowptr[w + 1];
    float a = 0.f;
    int i = beg;
    for (; i + 32 <= end; i += 32) {
        int sv = g_srcs[i + lane];
#pragma unroll
        for (int j = 0; j < 32; ++j) {
            int sj = __shfl_sync(0xffffffffu, sv, j);
            if (lane < DOUT) a += g_hl[(size_t)sj * DOUT + lane];
        }
    }
    int rem = end - i;
    if (rem > 0) {
        int sv = (lane < rem) ? g_srcs[i + lane] : 0;
        for (int j = 0; j < rem; ++j) {
            int sj = __shfl_sync(0xffffffffu, sv, j);
            if (lane < DOUT) a += g_hl[(size_t)sj * DOUT + lane];
        }
    }
    float inv = (end > beg) ? 1.f / (float)(end - beg) : 0.f;
    float v = 0.f;
    if (lane < DOUT) v = a * inv + g_hr[(size_t)w * DOUT + lane];

    float m = (lane < DOUT) ? v : -INFINITY;
#pragma unroll
    for (int o = 16; o >= 1; o >>= 1) m = fmaxf(m, __shfl_xor_sync(0xffffffffu, m, o));
    float e = (lane < DOUT) ? expf(v - m) : 0.f;
#pragma unroll
    for (int o = 16; o >= 1; o >>= 1) e += __shfl_xor_sync(0xffffffffu, e, o);
    float l = m + logf(e);
    if (lane < DOUT) out[(size_t)w * DOUT + lane] = v - l;
}

// ---------------- launch -------------------------------------------------------
extern "C" void kernel_launch(void* const* d_in, const int* in_sizes, int n_in,
                              void* d_out, int out_size) {
    const float* x   = (const float*)d_in[0];
    const int*   ei  = (const int*)  d_in[1];
    const float* W1l = (const float*)d_in[2];
    const float* b1  = (const float*)d_in[3];
    const float* W1r = (const float*)d_in[4];
    const float* W2l = (const float*)d_in[5];
    const float* b2  = (const float*)d_in[6];
    const float* W2r = (const float*)d_in[7];
    float* out = (float*)d_out;

    const int* src = ei;
    const int* dst = ei + NE;

    const int nblk_node = (NN + 255) / 256;       // 391
    const int nblk_edge = (NE + 255) / 256;       // 12500
    const int nblk_warp = (NN + 7) / 8;           // 12500 (8 warps/block)

    // CSR build
    k_zero_deg<<<128, 256>>>();
    k_hist<<<nblk_edge, 256>>>(dst);
    k_scan1<<<NBLK_SCAN, 256>>>();
    k_scan2<<<1, 1>>>();
    k_scan3<<<NBLK_SCAN, 256>>>();
    k_place<<<nblk_edge, 256>>>(src, dst);

    // layer 1
    k_gemm_xl<<<nblk_node, 256>>>(x, W1l);
    k_agg1<<<nblk_warp, 256>>>();
    k_gemm_h<<<nblk_node, 256>>>(x, W1r, b1);

    // layer 2 + log_softmax
    k_gemm_l2<<<nblk_node, 256>>>(W2l, W2r, b2);
    k_agg2_final<<<nblk_warp, 256>>>(out);
}